// round 16
// baseline (speedup 1.0000x reference)
#include <cuda_runtime.h>
#include <cuda_bf16.h>
#include <cuda_fp16.h>
#include <cstdint>

// ---------------- problem constants ----------------
#define BATCH    8192
#define IN_DIM   512
#define NUM_TREE 64
#define NI       31
#define NL       32
#define ODIM     16

// ---------------- GEMM1 tiling (bf16 m16n8k16, fragment-major, direct LDG) ----------------
#define BM       64          // 4 mtiles
#define BN       128         // 4 trees * 32 padded cols (16 ntiles)
#define NK16     (IN_DIM / 16)   // 32 k16 steps
#define THREADS  256         // 8 warps: 2 m-groups x 4 n-groups, 32x32 warp tiles
#define NGRP     16          // N groups (16 * 128 = 2048 padded nodes)

// smem: p buffer + route A-fragments + bias
#define P_PITCH   133
#define UOFF_P    0u                           // float[64*133]  = 34048 B
#define UOFF_AF   34048u                       // u32[4*8*32*4]  = 16384 B (route frags)
#define UOFF_BIAS 50432u                       // float[128]     = 512 B
#define SMEM_TOTAL 50944u                      // x2 CTAs = ~102 KB/SM

// ---------------- device scratch ----------------
// A fragments (bf16x2 words): [512 mtiles][32 k16][32 lanes][4 regs] = 8.4 MB
__device__ __align__(16) uint32_t g_A[(size_t)BATCH * IN_DIM / 2];
// B fragments (bf16x2 words): [256 ntiles][32 k16][32 lanes][2 regs] = 2 MB
__device__ __align__(16) uint32_t g_B[(size_t)2048 * IN_DIM / 2];
// Leaf B fragments (fp16x2): [16 grp][2 nt][8 s][32 lane][2 reg] = 16384 u32
__device__ __align__(16) uint32_t g_LB[16384];
__device__ __align__(16) float g_bp[2048];
__device__ __align__(16) float g_leafs_sm[NUM_TREE * NL * ODIM];
__device__ __align__(16) float g_outp[(size_t)NGRP * BATCH * ODIM];  // 16 partials, 8 MB

// ---------------- helpers ----------------
__device__ __forceinline__ void ldg128(uint32_t* r, const uint32_t* p) {
    asm volatile("ld.global.nc.v4.b32 {%0,%1,%2,%3}, [%4];"
                 : "=r"(r[0]), "=r"(r[1]), "=r"(r[2]), "=r"(r[3]) : "l"(p));
}
__device__ __forceinline__ void ldg64(uint32_t* r, const uint32_t* p) {
    asm volatile("ld.global.nc.v2.b32 {%0,%1}, [%2];" : "=r"(r[0]), "=r"(r[1]) : "l"(p));
}
__device__ __forceinline__ void mma_bf16(float& c0, float& c1, float& c2, float& c3,
                                         uint32_t a0, uint32_t a1, uint32_t a2, uint32_t a3,
                                         uint32_t b0, uint32_t b1) {
    asm volatile("mma.sync.aligned.m16n8k16.row.col.f32.bf16.bf16.f32 "
                 "{%0,%1,%2,%3}, {%4,%5,%6,%7}, {%8,%9}, {%0,%1,%2,%3};"
                 : "+f"(c0), "+f"(c1), "+f"(c2), "+f"(c3)
                 : "r"(a0), "r"(a1), "r"(a2), "r"(a3), "r"(b0), "r"(b1));
}
__device__ __forceinline__ void mma_fp16(float& c0, float& c1, float& c2, float& c3,
                                         uint32_t a0, uint32_t a1, uint32_t a2, uint32_t a3,
                                         uint32_t b0, uint32_t b1) {
    asm volatile("mma.sync.aligned.m16n8k16.row.col.f32.f16.f16.f32 "
                 "{%0,%1,%2,%3}, {%4,%5,%6,%7}, {%8,%9}, {%0,%1,%2,%3};"
                 : "+f"(c0), "+f"(c1), "+f"(c2), "+f"(c3)
                 : "r"(a0), "r"(a1), "r"(a2), "r"(a3), "r"(b0), "r"(b1));
}
__device__ __forceinline__ uint32_t pack_bf16x2(float lo, float hi) {
    __nv_bfloat162 h;
    h.x = __float2bfloat16(lo);
    h.y = __float2bfloat16(hi);
    return *(const uint32_t*)&h;
}

// ---------------- prep kernels ----------------
__global__ void leafs_softmax_kernel(const float* __restrict__ leafs) {
    int i = blockIdx.x * blockDim.x + threadIdx.x;
    if (i >= NUM_TREE * NL) return;
    const float* src = leafs + i * ODIM;
    float m = src[0];
#pragma unroll
    for (int o = 1; o < ODIM; o++) m = fmaxf(m, src[o]);
    float e[ODIM], sum = 0.f;
#pragma unroll
    for (int o = 0; o < ODIM; o++) { e[o] = __expf(src[o] - m); sum += e[o]; }
    float inv = 1.0f / sum;
#pragma unroll
    for (int o = 0; o < ODIM; o++) g_leafs_sm[i * ODIM + o] = e[o] * inv;
}

// leafs_sm -> fp16 B fragments for GEMM2 (m16n8k16, col-major B):
// linear i = (((grp*2+nt)*8+s)*32+lane)*2+reg ; 16 groups x 4 trees each
__global__ void prep_leaf_kernel() {
    int i = blockIdx.x * blockDim.x + threadIdx.x;   // 0..16383
    int reg  = i & 1;
    int lane = (i >> 1) & 31;
    int s    = (i >> 6) & 7;
    int nt   = (i >> 9) & 1;
    int grp  = i >> 10;
    int n  = nt * 8 + (lane >> 2);
    int k0 = s * 16 + (lane & 3) * 2 + reg * 8;      // even, 0..127
    int tree = grp * 4 + (k0 >> 5);
    int leaf = k0 & 31;
    float v0 = g_leafs_sm[(tree * 32 + leaf) * ODIM + n];
    float v1 = g_leafs_sm[(tree * 32 + leaf + 1) * ODIM + n];
    __half2 h = __floats2half2_rn(v0, v1);
    g_LB[i] = *(const uint32_t*)&h;
}

// x -> bf16x2 A fragments, m16n8k16 layout: [mtile][k16][lane][reg]
__global__ void prep_x_kernel(const float* __restrict__ x) {
    int i = blockIdx.x * blockDim.x + threadIdx.x;   // 0 .. BATCH*IN_DIM/2-1
    int mtile = i >> 12;
    int rem   = i & 4095;
    int step  = rem >> 7;
    int rem2  = rem & 127;
    int lane  = rem2 >> 2;
    int reg   = rem2 & 3;
    int g = lane >> 2, t = lane & 3;
    int row = mtile * 16 + g + (reg & 1) * 8;
    int k0  = step * 16 + 2 * t + ((reg >> 1) & 1) * 8;
    const float* xp = x + (size_t)row * IN_DIM + k0;
    g_A[i] = pack_bf16x2(xp[0], xp[1]);
}

// W (tree-permuted, node31 zero) -> bf16x2 B fragments: [ntile][k16][lane][reg]
__global__ void prep_w_kernel(const float* __restrict__ W, const float* __restrict__ b) {
    int i = blockIdx.x * blockDim.x + threadIdx.x;   // 0 .. 2048*IN_DIM/2-1
    int ntile = i >> 11;
    int rem   = i & 2047;
    int step  = rem >> 6;
    int rem2  = rem & 63;
    int lane  = rem2 >> 1;
    int reg   = rem2 & 1;
    int g = lane >> 2, t = lane & 3;
    int n = ntile * 8 + g;
    int tree = n >> 5, ii = n & 31;
    int k0 = step * 16 + 2 * t + reg * 8;
    float v0 = 0.f, v1 = 0.f;
    if (ii < 31) {
        const float* wp = W + (size_t)(tree * 31 + ii) * IN_DIM + k0;
        v0 = wp[0]; v1 = wp[1];
    }
    g_B[i] = pack_bf16x2(v0, v1);
    if (step == 0 && t == 0 && reg == 0)
        g_bp[n] = (ii < 31) ? b[tree * 31 + ii] : 0.f;
}

// ---------------- fused GEMM1 + routing + GEMM2 kernel, 2 CTAs/SM ----------------
__global__ __launch_bounds__(THREADS, 2)
void dndf_mma_kernel() {
    extern __shared__ char smem[];

    const int tid = threadIdx.x;
    const int wid = tid >> 5;
    const int lid = tid & 31;
    const int wm = wid & 1;          // 2 m-groups of 32 rows (2 mtiles)
    const int wn = wid >> 1;         // 4 n-groups of 32 cols (4 ntiles)
    const int bm4  = blockIdx.y * 4;    // first mtile of CTA
    const int bn16 = blockIdx.x * 16;   // first ntile of CTA
    const int mrow_base = blockIdx.y * BM;
    const int ncol_base = blockIdx.x * BN;

    float*    p_s    = (float*)(smem + UOFF_P);
    uint32_t* af     = (uint32_t*)(smem + UOFF_AF);
    float*    bias_s = (float*)(smem + UOFF_BIAS);

    // ---- stage bias BEFORE mainloop (sync after mainloop covers it) ----
    if (tid < 128) bias_s[tid] = g_bp[ncol_base + tid];

    // ---- fragment pointers (GEMM1) ----
    const uint32_t* a_ptr = g_A + ((size_t)(bm4 + wm * 2) * 4096) + lid * 4;
    const uint32_t* b_ptr = g_B + ((size_t)(bn16 + wn * 4) * 2048) + lid * 2;

    float acc[2][4][4];
#pragma unroll
    for (int i = 0; i < 2; i++)
#pragma unroll
        for (int j = 0; j < 4; j++)
#pragma unroll
            for (int r = 0; r < 4; r++) acc[i][j][r] = 0.f;

    uint32_t a[2][2][4], b[2][4][2];
#pragma unroll
    for (int mi = 0; mi < 2; mi++) ldg128(a[0][mi], a_ptr + mi * 4096);
#pragma unroll
    for (int nb = 0; nb < 4; nb++) ldg64(b[0][nb], b_ptr + nb * 2048);

#pragma unroll 1
    for (int k = 0; k < NK16; k += 2) {
        {
            const uint32_t* ap = a_ptr + (size_t)(k + 1) * 128;
            const uint32_t* bp = b_ptr + (size_t)(k + 1) * 64;
#pragma unroll
            for (int mi = 0; mi < 2; mi++) ldg128(a[1][mi], ap + mi * 4096);
#pragma unroll
            for (int nb = 0; nb < 4; nb++) ldg64(b[1][nb], bp + nb * 2048);
#pragma unroll
            for (int mi = 0; mi < 2; mi++)
#pragma unroll
                for (int nb = 0; nb < 4; nb++)
                    mma_bf16(acc[mi][nb][0], acc[mi][nb][1], acc[mi][nb][2], acc[mi][nb][3],
                             a[0][mi][0], a[0][mi][1], a[0][mi][2], a[0][mi][3],
                             b[0][nb][0], b[0][nb][1]);
        }
        {
            if (k + 2 < NK16) {
                const uint32_t* ap = a_ptr + (size_t)(k + 2) * 128;
                const uint32_t* bp = b_ptr + (size_t)(k + 2) * 64;
#pragma unroll
                for (int mi = 0; mi < 2; mi++) ldg128(a[0][mi], ap + mi * 4096);
#pragma unroll
                for (int nb = 0; nb < 4; nb++) ldg64(b[0][nb], bp + nb * 2048);
            }
#pragma unroll
            for (int mi = 0; mi < 2; mi++)
#pragma unroll
                for (int nb = 0; nb < 4; nb++)
                    mma_bf16(acc[mi][nb][0], acc[mi][nb][1], acc[mi][nb][2], acc[mi][nb][3],
                             a[1][mi][0], a[1][mi][1], a[1][mi][2], a[1][mi][3],
                             b[1][nb][0], b[1][nb][1]);
        }
    }

    __syncthreads();   // bias staged; p_s free to fill

    // ---- sigmoid(acc + bias) -> p_s, tree-interleaved: p_s[row][node*4 + tree] ----
#pragma unroll
    for (int mi = 0; mi < 2; mi++) {
#pragma unroll
        for (int nb = 0; nb < 4; nb++) {
            const int colb = wn * 32 + nb * 8 + (lid & 3) * 2;
            const int rowb = wm * 32 + mi * 16 + (lid >> 2);
#pragma unroll
            for (int r = 0; r < 4; r++) {
                const int row = rowb + (r >> 1) * 8;
                const int col = colb + (r & 1);           // 0..127 = tree*32 + node
                const int icol = (col & 31) * 4 + (col >> 5);
                const float v = acc[mi][nb][r] + bias_s[col];
                p_s[row * P_PITCH + icol] = 1.0f / (1.0f + __expf(-v));
            }
        }
    }
    __syncthreads();

    // ---- routing: 256 tasks (row, tree), one per thread; routes -> af fp16 frags ----
    // af layout: [mt(4)][s(8)][lane(32)][reg(4)] u32
    {
        const int t = lid & 3;
        const int row = wid * 8 + (lid >> 2);
        const float* P = &p_s[row * P_PITCH + t];   // node i at P[i*4]

        float bb[4], cc[8], dd[16];
        {
            float p0 = P[0];
            float p1 = P[4], p2 = P[8];
            float s01 = p0 * p1;
            float s02 = p2 - p0 * p2;
            bb[0] = s01;         bb[1] = p0 - s01;
            bb[2] = s02;         bb[3] = (1.0f - p0) - s02;
        }
#pragma unroll
        for (int q = 0; q < 4; q++) {
            float pv = P[(3 + q) * 4];
            float s = bb[q] * pv;
            cc[2 * q] = s; cc[2 * q + 1] = bb[q] - s;
        }
#pragma unroll
        for (int q = 0; q < 8; q++) {
            float pv = P[(7 + q) * 4];
            float s = cc[q] * pv;
            dd[2 * q] = s; dd[2 * q + 1] = cc[q] - s;
        }

        const int mt = row >> 4, g = row & 7, hi = (row >> 3) & 1;
#pragma unroll
        for (int q = 0; q < 16; q++) {
            float pv = P[(15 + q) * 4];
            float r0 = dd[q] * pv;
            float r1 = dd[q] - r0;
            __half2 h = __floats2half2_rn(r0, r1);
            const int s  = 2 * t + (q >> 3);
            const int idx = ((mt * 8 + s) * 32 + g * 4 + (q & 3)) * 4
                            + ((q >> 2) & 1) * 2 + hi;
            af[idx] = *(const uint32_t*)&h;
        }
    }
    __syncthreads();

    // ---- GEMM2: out_partial[64x16] = routes[64x128] @ leafs_fp16[128x16] ----
    // 8 warps = 4 mtiles x 2 ntiles; per warp: 8 k16 steps.
    {
        const int mt = wid >> 1;
        const int nt = wid & 1;
        uint32_t bf[8][2];
        const uint32_t* lb = g_LB + (((size_t)(blockIdx.x * 2 + nt) * 8) * 32 + lid) * 2;
#pragma unroll
        for (int s = 0; s < 8; s++) ldg64(bf[s], lb + s * 64);

        float c0 = 0.f, c1 = 0.f, c2 = 0.f, c3 = 0.f;
#pragma unroll
        for (int s = 0; s < 8; s++) {
            uint4 a4 = *(const uint4*)&af[((mt * 8 + s) * 32 + lid) * 4];
            mma_fp16(c0, c1, c2, c3, a4.x, a4.y, a4.z, a4.w, bf[s][0], bf[s][1]);
        }

        const int row0 = mrow_base + mt * 16 + (lid >> 2);
        const int n0 = nt * 8 + (lid & 3) * 2;
        float* op = &g_outp[((size_t)blockIdx.x * BATCH + row0) * ODIM + n0];
        *(float2*)op = make_float2(c0, c1);
        *(float2*)(op + 8 * ODIM) = make_float2(c2, c3);
    }
}

// ---------------- final reduce over the 16 partials ----------------
__global__ void reduce_kernel(float* __restrict__ out) {
    int i = blockIdx.x * blockDim.x + threadIdx.x;   // 32768 float4s
    float4 acc = make_float4(0.f, 0.f, 0.f, 0.f);
#pragma unroll
    for (int g = 0; g < NGRP; g++) {
        float4 v = ((const float4*)g_outp)[(size_t)g * (BATCH * 4) + i];
        acc.x += v.x; acc.y += v.y; acc.z += v.z; acc.w += v.w;
    }
    const float s = 1.0f / NUM_TREE;
    ((float4*)out)[i] = make_float4(acc.x * s, acc.y * s, acc.z * s, acc.w * s);
}

// ---------------- launch ----------------
extern "C" void kernel_launch(void* const* d_in, const int* in_sizes, int n_in,
                              void* d_out, int out_size) {
    const float* x     = (const float*)d_in[0];   // [8192, 512]
    const float* W     = (const float*)d_in[1];   // [1984, 512]
    const float* b     = (const float*)d_in[2];   // [1984]
    const float* leafs = (const float*)d_in[3];   // [64, 32, 16]
    float* out = (float*)d_out;                   // [8192, 16]

    leafs_softmax_kernel<<<(NUM_TREE * NL + 255) / 256, 256>>>(leafs);
    prep_leaf_kernel<<<16384 / 256, 256>>>();
    prep_x_kernel<<<(BATCH * IN_DIM / 2) / 256, 256>>>(x);
    prep_w_kernel<<<(2048 * IN_DIM / 2) / 256, 256>>>(W, b);

    cudaFuncSetAttribute(dndf_mma_kernel,
                         cudaFuncAttributeMaxDynamicSharedMemorySize, SMEM_TOTAL);
    dndf_mma_kernel<<<dim3(NGRP, BATCH / BM), THREADS, SMEM_TOTAL>>>();

    reduce_kernel<<<(BATCH * 4) / 256, 256>>>(out);
}

// round 17
// speedup vs baseline: 1.1691x; 1.1691x over previous
#include <cuda_runtime.h>
#include <cuda_bf16.h>
#include <cuda_fp16.h>
#include <cstdint>

// ---------------- problem constants ----------------
#define BATCH    8192
#define IN_DIM   512
#define NUM_TREE 64
#define NI       31
#define NL       32
#define ODIM     16

// ---------------- GEMM1 tiling (bf16 m16n8k16, fragment-major, direct LDG) ----------------
#define BM       64          // 4 mtiles
#define BN       128         // 4 trees * 32 padded cols (16 ntiles)
#define NK16     (IN_DIM / 16)   // 32 k16 steps
#define THREADS  256         // 8 warps: 2 m-groups x 4 n-groups, 32x32 warp tiles
#define NGRP     16          // N groups (16 * 128 = 2048 padded nodes)

// smem: p buffer + route A-fragments + bias
#define P_PITCH   133
#define UOFF_P    0u                           // float[64*133]  = 34048 B
#define UOFF_AF   34048u                       // u32[4*8*32*4]  = 16384 B (route frags)
#define UOFF_BIAS 50432u                       // float[128]     = 512 B
#define SMEM_TOTAL 50944u                      // x2 CTAs = ~102 KB/SM

// ---------------- device scratch ----------------
// A fragments (bf16x2 words): [512 mtiles][32 k16][32 lanes][4 regs] = 8.4 MB
__device__ __align__(16) uint32_t g_A[(size_t)BATCH * IN_DIM / 2];
// B fragments (bf16x2 words): [256 ntiles][32 k16][32 lanes][2 regs] = 2 MB
__device__ __align__(16) uint32_t g_B[(size_t)2048 * IN_DIM / 2];
// Leaf B fragments (fp16x2): [16 grp][2 nt][8 s][32 lane][2 reg] = 16384 u32
__device__ __align__(16) uint32_t g_LB[16384];
__device__ __align__(16) float g_bp[2048];
__device__ __align__(16) float g_leafs_sm[NUM_TREE * NL * ODIM];
__device__ __align__(16) float g_outp[(size_t)NGRP * BATCH * ODIM];  // 16 partials, 8 MB

// ---------------- helpers ----------------
__device__ __forceinline__ void ldg128(uint32_t* r, const uint32_t* p) {
    asm volatile("ld.global.nc.v4.b32 {%0,%1,%2,%3}, [%4];"
                 : "=r"(r[0]), "=r"(r[1]), "=r"(r[2]), "=r"(r[3]) : "l"(p));
}
__device__ __forceinline__ void ldg64(uint32_t* r, const uint32_t* p) {
    asm volatile("ld.global.nc.v2.b32 {%0,%1}, [%2];" : "=r"(r[0]), "=r"(r[1]) : "l"(p));
}
__device__ __forceinline__ void mma_bf16(float& c0, float& c1, float& c2, float& c3,
                                         uint32_t a0, uint32_t a1, uint32_t a2, uint32_t a3,
                                         uint32_t b0, uint32_t b1) {
    asm volatile("mma.sync.aligned.m16n8k16.row.col.f32.bf16.bf16.f32 "
                 "{%0,%1,%2,%3}, {%4,%5,%6,%7}, {%8,%9}, {%0,%1,%2,%3};"
                 : "+f"(c0), "+f"(c1), "+f"(c2), "+f"(c3)
                 : "r"(a0), "r"(a1), "r"(a2), "r"(a3), "r"(b0), "r"(b1));
}
__device__ __forceinline__ void mma_fp16(float& c0, float& c1, float& c2, float& c3,
                                         uint32_t a0, uint32_t a1, uint32_t a2, uint32_t a3,
                                         uint32_t b0, uint32_t b1) {
    asm volatile("mma.sync.aligned.m16n8k16.row.col.f32.f16.f16.f32 "
                 "{%0,%1,%2,%3}, {%4,%5,%6,%7}, {%8,%9}, {%0,%1,%2,%3};"
                 : "+f"(c0), "+f"(c1), "+f"(c2), "+f"(c3)
                 : "r"(a0), "r"(a1), "r"(a2), "r"(a3), "r"(b0), "r"(b1));
}
__device__ __forceinline__ uint32_t pack_bf16x2(float lo, float hi) {
    __nv_bfloat162 h;
    h.x = __float2bfloat16(lo);
    h.y = __float2bfloat16(hi);
    return *(const uint32_t*)&h;
}

// ---------------- prep kernels ----------------
__global__ void leafs_softmax_kernel(const float* __restrict__ leafs) {
    int i = blockIdx.x * blockDim.x + threadIdx.x;
    if (i >= NUM_TREE * NL) return;
    const float* src = leafs + i * ODIM;
    float m = src[0];
#pragma unroll
    for (int o = 1; o < ODIM; o++) m = fmaxf(m, src[o]);
    float e[ODIM], sum = 0.f;
#pragma unroll
    for (int o = 0; o < ODIM; o++) { e[o] = __expf(src[o] - m); sum += e[o]; }
    float inv = 1.0f / sum;
#pragma unroll
    for (int o = 0; o < ODIM; o++) g_leafs_sm[i * ODIM + o] = e[o] * inv;
}

// leafs_sm -> fp16 B fragments for GEMM2: i = (((grp*2+nt)*8+s)*32+lane)*2+reg
__global__ void prep_leaf_kernel() {
    int i = blockIdx.x * blockDim.x + threadIdx.x;   // 0..16383
    int reg  = i & 1;
    int lane = (i >> 1) & 31;
    int s    = (i >> 6) & 7;
    int nt   = (i >> 9) & 1;
    int grp  = i >> 10;
    int n  = nt * 8 + (lane >> 2);
    int k0 = s * 16 + (lane & 3) * 2 + reg * 8;      // even, 0..127
    int tree = grp * 4 + (k0 >> 5);
    int leaf = k0 & 31;
    float v0 = g_leafs_sm[(tree * 32 + leaf) * ODIM + n];
    float v1 = g_leafs_sm[(tree * 32 + leaf + 1) * ODIM + n];
    __half2 h = __floats2half2_rn(v0, v1);
    g_LB[i] = *(const uint32_t*)&h;
}

// x -> bf16x2 A fragments; one thread emits a full 16B fragment (4 regs)
__global__ void prep_x_kernel(const float* __restrict__ x) {
    int i = blockIdx.x * blockDim.x + threadIdx.x;   // 0 .. BATCH*IN_DIM/8-1
    int mtile = i >> 10;           // 1024 threads per mtile (32 steps * 32 lanes)
    int rem   = i & 1023;
    int step  = rem >> 5;
    int lane  = rem & 31;
    int g = lane >> 2, t = lane & 3;
    int row0 = mtile * 16 + g;
    int k0   = step * 16 + 2 * t;
    const float* xp = x + (size_t)row0 * IN_DIM + k0;
    float2 v00 = *(const float2*)(xp);                        // (row0,   k0)
    float2 v10 = *(const float2*)(xp + 8 * IN_DIM);           // (row0+8, k0)
    float2 v01 = *(const float2*)(xp + 8);                    // (row0,   k0+8)
    float2 v11 = *(const float2*)(xp + 8 * IN_DIM + 8);       // (row0+8, k0+8)
    uint4 out;
    out.x = pack_bf16x2(v00.x, v00.y);
    out.y = pack_bf16x2(v10.x, v10.y);
    out.z = pack_bf16x2(v01.x, v01.y);
    out.w = pack_bf16x2(v11.x, v11.y);
    *(uint4*)&g_A[(size_t)i * 4] = out;
}

// W (tree-permuted, node31 zero) -> bf16x2 B fragments; one thread emits 8B (2 regs)
__global__ void prep_w_kernel(const float* __restrict__ W, const float* __restrict__ b) {
    int i = blockIdx.x * blockDim.x + threadIdx.x;   // 0 .. 2048*IN_DIM/4-1
    int ntile = i >> 10;           // 1024 threads per ntile
    int rem   = i & 1023;
    int step  = rem >> 5;
    int lane  = rem & 31;
    int g = lane >> 2, t = lane & 3;
    int n = ntile * 8 + g;
    int tree = n >> 5, ii = n & 31;
    int k0 = step * 16 + 2 * t;
    uint2 out;
    if (ii < 31) {
        const float* wp = W + (size_t)(tree * 31 + ii) * IN_DIM + k0;
        float2 v0 = *(const float2*)(wp);
        float2 v1 = *(const float2*)(wp + 8);
        out.x = pack_bf16x2(v0.x, v0.y);
        out.y = pack_bf16x2(v1.x, v1.y);
    } else {
        out.x = 0u; out.y = 0u;
    }
    *(uint2*)&g_B[(size_t)i * 2] = out;
    if (step == 0 && t == 0)
        g_bp[n] = (ii < 31) ? b[tree * 31 + ii] : 0.f;
}

// ---------------- fused GEMM1 + routing + GEMM2 kernel, 2 CTAs/SM ----------------
__global__ __launch_bounds__(THREADS, 2)
void dndf_mma_kernel() {
    extern __shared__ char smem[];

    const int tid = threadIdx.x;
    const int wid = tid >> 5;
    const int lid = tid & 31;
    const int wm = wid & 1;          // 2 m-groups of 32 rows (2 mtiles)
    const int wn = wid >> 1;         // 4 n-groups of 32 cols (4 ntiles)
    const int bm4  = blockIdx.y * 4;    // first mtile of CTA
    const int bn16 = blockIdx.x * 16;   // first ntile of CTA
    const int mrow_base = blockIdx.y * BM;
    const int ncol_base = blockIdx.x * BN;

    float*    p_s    = (float*)(smem + UOFF_P);
    uint32_t* af     = (uint32_t*)(smem + UOFF_AF);
    float*    bias_s = (float*)(smem + UOFF_BIAS);

    if (tid < 128) bias_s[tid] = g_bp[ncol_base + tid];

    const uint32_t* a_ptr = g_A + ((size_t)(bm4 + wm * 2) * 4096) + lid * 4;
    const uint32_t* b_ptr = g_B + ((size_t)(bn16 + wn * 4) * 2048) + lid * 2;

    float acc[2][4][4];
#pragma unroll
    for (int i = 0; i < 2; i++)
#pragma unroll
        for (int j = 0; j < 4; j++)
#pragma unroll
            for (int r = 0; r < 4; r++) acc[i][j][r] = 0.f;

    // ---- 3-stage register ring, prefetch distance 2 ----
    uint32_t a[3][2][4], b[3][4][2];
#pragma unroll
    for (int s = 0; s < 2; s++) {
#pragma unroll
        for (int mi = 0; mi < 2; mi++) ldg128(a[s][mi], a_ptr + (size_t)s * 128 + mi * 4096);
#pragma unroll
        for (int nb = 0; nb < 4; nb++) ldg64(b[s][nb], b_ptr + (size_t)s * 64 + nb * 2048);
    }

#pragma unroll
    for (int k = 0; k < NK16; k++) {
        const int cur = k % 3;
        const int pre = (k + 2) % 3;
        if (k + 2 < NK16) {
            const uint32_t* ap = a_ptr + (size_t)(k + 2) * 128;
            const uint32_t* bp = b_ptr + (size_t)(k + 2) * 64;
#pragma unroll
            for (int mi = 0; mi < 2; mi++) ldg128(a[pre][mi], ap + mi * 4096);
#pragma unroll
            for (int nb = 0; nb < 4; nb++) ldg64(b[pre][nb], bp + nb * 2048);
        }
#pragma unroll
        for (int mi = 0; mi < 2; mi++)
#pragma unroll
            for (int nb = 0; nb < 4; nb++)
                mma_bf16(acc[mi][nb][0], acc[mi][nb][1], acc[mi][nb][2], acc[mi][nb][3],
                         a[cur][mi][0], a[cur][mi][1], a[cur][mi][2], a[cur][mi][3],
                         b[cur][nb][0], b[cur][nb][1]);
    }

    __syncthreads();   // bias staged; p_s free to fill

    // ---- sigmoid(acc + bias) -> p_s, tree-interleaved: p_s[row][node*4 + tree] ----
#pragma unroll
    for (int mi = 0; mi < 2; mi++) {
#pragma unroll
        for (int nb = 0; nb < 4; nb++) {
            const int colb = wn * 32 + nb * 8 + (lid & 3) * 2;
            const int rowb = wm * 32 + mi * 16 + (lid >> 2);
#pragma unroll
            for (int r = 0; r < 4; r++) {
                const int row = rowb + (r >> 1) * 8;
                const int col = colb + (r & 1);           // 0..127 = tree*32 + node
                const int icol = (col & 31) * 4 + (col >> 5);
                const float v = acc[mi][nb][r] + bias_s[col];
                p_s[row * P_PITCH + icol] = 1.0f / (1.0f + __expf(-v));
            }
        }
    }
    __syncthreads();

    // ---- routing: 256 tasks (row, tree), one per thread; routes -> af fp16 frags ----
    {
        const int t = lid & 3;
        const int row = wid * 8 + (lid >> 2);
        const float* P = &p_s[row * P_PITCH + t];   // node i at P[i*4]

        float bb[4], cc[8], dd[16];
        {
            float p0 = P[0];
            float p1 = P[4], p2 = P[8];
            float s01 = p0 * p1;
            float s02 = p2 - p0 * p2;
            bb[0] = s01;         bb[1] = p0 - s01;
            bb[2] = s02;         bb[3] = (1.0f - p0) - s02;
        }
#pragma unroll
        for (int q = 0; q < 4; q++) {
            float pv = P[(3 + q) * 4];
            float s = bb[q] * pv;
            cc[2 * q] = s; cc[2 * q + 1] = bb[q] - s;
        }
#pragma unroll
        for (int q = 0; q < 8; q++) {
            float pv = P[(7 + q) * 4];
            float s = cc[q] * pv;
            dd[2 * q] = s; dd[2 * q + 1] = cc[q] - s;
        }

        const int mt = row >> 4, g = row & 7, hi = (row >> 3) & 1;
#pragma unroll
        for (int q = 0; q < 16; q++) {
            float pv = P[(15 + q) * 4];
            float r0 = dd[q] * pv;
            float r1 = dd[q] - r0;
            __half2 h = __floats2half2_rn(r0, r1);
            const int s  = 2 * t + (q >> 3);
            const int idx = ((mt * 8 + s) * 32 + g * 4 + (q & 3)) * 4
                            + ((q >> 2) & 1) * 2 + hi;
            af[idx] = *(const uint32_t*)&h;
        }
    }
    __syncthreads();

    // ---- GEMM2: out_partial[64x16] = routes[64x128] @ leafs_fp16[128x16] ----
    {
        const int mt = wid >> 1;
        const int nt = wid & 1;
        uint32_t bf[8][2];
        const uint32_t* lb = g_LB + (((size_t)(blockIdx.x * 2 + nt) * 8) * 32 + lid) * 2;
#pragma unroll
        for (int s = 0; s < 8; s++) ldg64(bf[s], lb + s * 64);

        float c0 = 0.f, c1 = 0.f, c2 = 0.f, c3 = 0.f;
#pragma unroll
        for (int s = 0; s < 8; s++) {
            uint4 a4 = *(const uint4*)&af[((mt * 8 + s) * 32 + lid) * 4];
            mma_fp16(c0, c1, c2, c3, a4.x, a4.y, a4.z, a4.w, bf[s][0], bf[s][1]);
        }

        const int row0 = mrow_base + mt * 16 + (lid >> 2);
        const int n0 = nt * 8 + (lid & 3) * 2;
        float* op = &g_outp[((size_t)blockIdx.x * BATCH + row0) * ODIM + n0];
        *(float2*)op = make_float2(c0, c1);
        *(float2*)(op + 8 * ODIM) = make_float2(c2, c3);
    }
}

// ---------------- final reduce over the 16 partials ----------------
__global__ void reduce_kernel(float* __restrict__ out) {
    int i = blockIdx.x * blockDim.x + threadIdx.x;   // 32768 float4s
    float4 acc = make_float4(0.f, 0.f, 0.f, 0.f);
#pragma unroll
    for (int g = 0; g < NGRP; g++) {
        float4 v = ((const float4*)g_outp)[(size_t)g * (BATCH * 4) + i];
        acc.x += v.x; acc.y += v.y; acc.z += v.z; acc.w += v.w;
    }
    const float s = 1.0f / NUM_TREE;
    ((float4*)out)[i] = make_float4(acc.x * s, acc.y * s, acc.z * s, acc.w * s);
}

// ---------------- launch ----------------
extern "C" void kernel_launch(void* const* d_in, const int* in_sizes, int n_in,
                              void* d_out, int out_size) {
    const float* x     = (const float*)d_in[0];   // [8192, 512]
    const float* W     = (const float*)d_in[1];   // [1984, 512]
    const float* b     = (const float*)d_in[2];   // [1984]
    const float* leafs = (const float*)d_in[3];   // [64, 32, 16]
    float* out = (float*)d_out;                   // [8192, 16]

    leafs_softmax_kernel<<<(NUM_TREE * NL + 255) / 256, 256>>>(leafs);
    prep_leaf_kernel<<<16384 / 256, 256>>>();
    prep_x_kernel<<<(BATCH * IN_DIM / 8) / 256, 256>>>(x);
    prep_w_kernel<<<(2048 * IN_DIM / 4) / 256, 256>>>(W, b);

    cudaFuncSetAttribute(dndf_mma_kernel,
                         cudaFuncAttributeMaxDynamicSharedMemorySize, SMEM_TOTAL);
    dndf_mma_kernel<<<dim3(NGRP, BATCH / BM), THREADS, SMEM_TOTAL>>>();

    reduce_kernel<<<(BATCH * 4) / 256, 256>>>(out);
}